// round 15
// baseline (speedup 1.0000x reference)
#include <cuda_runtime.h>
#include <cstdint>

#define TT 100
#define DD 32
#define AA 16
#define NPAIR 4950
#define NTASK 156
#define HTASK 78            // chunks per half-element
#define NPP (NTASK*32)      // 4992, padded pair space
#define TTP 100
#define NTHREADS 128
#define NW (NTHREADS/32)
#define BSZ 1024

typedef unsigned long long ull;

// pair index table: (i<<8)|j for itertools.combinations order; dummies = (0,1)
__device__ __align__(16) int g_pairIJ[NPP];

// cross-CTA scratch: every slot rewritten each launch (deterministic)
__device__ float g_pool[BSZ*2][DD];   // unnormalized pooled halves
__device__ float g_sum[BSZ*2];        // 4x-replicated exp-sums
__device__ int   g_cnt[BSZ];          // arrival counters; zero before & after every launch

// small weights in constant memory
__constant__ __align__(16) float cb[AA];
__constant__ __align__(16) float ch[AA];
__constant__ float cW1[DD*16];
__constant__ float cb1[16];
__constant__ float cW2m[16*8];
__constant__ float cb2[8];
__constant__ float cWf[8];
__constant__ float cbf[1];

__global__ void setup_pairs_kernel() {
    int p = blockIdx.x * blockDim.x + threadIdx.x;
    if (p >= NPP) return;
    if (p >= NPAIR) { g_pairIJ[p] = 1; return; }   // dummy pair (0,1)
    float disc = (float)((2*TT-1)*(2*TT-1) - 8*p);
    int i = (int)(((float)(2*TT-1) - sqrtf(disc)) * 0.5f);
    if (i < 0) i = 0;
    if (i > TT-2) i = TT-2;
    while (i > 0    && (i*(2*TT-1-i))/2 > p) i--;
    while (i < TT-2 && ((i+1)*(2*TT-1-(i+1)))/2 <= p) i++;
    int off = (i*(2*TT-1-i))/2;
    int j = p - off + i + 1;
    g_pairIJ[p] = (i << 8) | j;
}

__device__ __forceinline__ void mma_tf32(
    float& c0, float& c1, float& c2, float& c3,
    unsigned a0, unsigned a1, unsigned a2, unsigned a3,
    unsigned b0, unsigned b1)
{
    asm volatile(
        "mma.sync.aligned.m16n8k8.row.col.f32.tf32.tf32.f32 "
        "{%0,%1,%2,%3}, {%4,%5,%6,%7}, {%8,%9}, {%0,%1,%2,%3};"
        : "+f"(c0), "+f"(c1), "+f"(c2), "+f"(c3)
        : "r"(a0), "r"(a1), "r"(a2), "r"(a3), "r"(b0), "r"(b1));
}

// =============== kernel: half-element MMA+pool, fused finisher ===============
__global__ __launch_bounds__(NTHREADS, 5) void afm_half_kernel(
    const int*   __restrict__ x,
    const float* __restrict__ Emb,
    const float* __restrict__ Wg,     // [32][16] row-major
    float* __restrict__ out)
{
    __shared__ __align__(16) float2 esT2[AA][TTP];  // [k2][t]: phys dims (2k2, 2k2+1)
    __shared__ int   xs[TT];
    __shared__ float red[NW];
    __shared__ float poolw[NW][DD];   // per-warp pooled partials
    __shared__ float poolv[DD];
    __shared__ float o1s[16];
    __shared__ float o2s[8];
    __shared__ int   sFinish;

    const int tid  = threadIdx.x;
    const int bid  = blockIdx.x;
    const int e    = bid >> 1;        // batch element
    const int hlf  = bid & 1;         // which half of the pair space
    const int lane = tid & 31;
    const int wid  = tid >> 5;
    const int tig  = lane & 3;
    const int gid  = lane >> 2;

    // ---- stage x indices, gather embeddings transposed: esT2[d2][t] ----
    if (tid < TT) xs[tid] = x[e*TT + tid];
    __syncthreads();
    for (int idx = tid; idx < TT*AA; idx += NTHREADS) {
        int t = idx >> 4, d2 = idx & 15;
        float2 v = ((const float2*)Emb)[(size_t)xs[t] * AA + d2];
        esT2[d2][t] = v;
    }

    // ---- per-lane W fragments. K-permutation: fragment col c in {tig, tig+4}
    // of k-block kb maps to PHYSICAL k = kb*8 + 2*tig + (c>=4).
    unsigned wf[4][2][2];
    #pragma unroll
    for (int kb = 0; kb < 4; kb++)
        #pragma unroll
        for (int nb = 0; nb < 2; nb++) {
            wf[kb][nb][0] = __float_as_uint(Wg[(kb*8 + 2*tig    )*16 + nb*8 + gid]);
            wf[kb][nb][1] = __float_as_uint(Wg[(kb*8 + 2*tig + 1)*16 + nb*8 + gid]);
        }
    float bb0[2], bb1[2], hh0[2], hh1[2];
    #pragma unroll
    for (int nb = 0; nb < 2; nb++) {
        bb0[nb] = cb[nb*8 + 2*tig];
        bb1[nb] = cb[nb*8 + 2*tig + 1];
        hh0[nb] = ch[nb*8 + 2*tig];
        hh1[nb] = ch[nb*8 + 2*tig + 1];
    }
    __syncthreads();

    // ============ FUSED: MMA logits -> E -> pooled, over this half ============
    float lsum = 0.f;                 // counts each E 4x (quad-replicated)
    ull acc[4];
    #pragma unroll
    for (int kb = 0; kb < 4; kb++) acc[kb] = 0ull;

    for (int t0 = wid; t0 < HTASK; t0 += NW) {
        const int p0 = (hlf*HTASK + t0)*32;
        int i_[4], j_[4];
        #pragma unroll
        for (int s = 0; s < 4; s++) {
            int v = g_pairIJ[p0 + gid + 8*s];
            i_[s] = v >> 8; j_[s] = v & 255;
        }
        float c[2][2][4];
        #pragma unroll
        for (int mb = 0; mb < 2; mb++)
            #pragma unroll
            for (int nb = 0; nb < 2; nb++) {
                c[mb][nb][0] = bb0[nb]; c[mb][nb][1] = bb1[nb];
                c[mb][nb][2] = bb0[nb]; c[mb][nb][3] = bb1[nb];
            }

        ull prod[4][4];   // [kb][s]: product f32x2 for pair row gid+8s, dims k2=kb*4+tig
        #pragma unroll
        for (int kb = 0; kb < 4; kb++) {
            const int k2 = kb*4 + tig;
            #pragma unroll
            for (int mb = 0; mb < 2; mb++) {
                ull eiA = *(const ull*)&esT2[k2][ i_[2*mb]   ];
                ull ejA = *(const ull*)&esT2[k2][ j_[2*mb]   ];
                ull eiB = *(const ull*)&esT2[k2][ i_[2*mb+1] ];
                ull ejB = *(const ull*)&esT2[k2][ j_[2*mb+1] ];
                ull prodA, prodB;
                asm("mul.rn.f32x2 %0, %1, %2;" : "=l"(prodA) : "l"(eiA), "l"(ejA));
                asm("mul.rn.f32x2 %0, %1, %2;" : "=l"(prodB) : "l"(eiB), "l"(ejB));
                prod[kb][2*mb]   = prodA;
                prod[kb][2*mb+1] = prodB;
                unsigned a0, a1, a2, a3;
                asm("mov.b64 {%0,%1}, %2;" : "=r"(a0), "=r"(a2) : "l"(prodA));
                asm("mov.b64 {%0,%1}, %2;" : "=r"(a1), "=r"(a3) : "l"(prodB));
                #pragma unroll
                for (int nb = 0; nb < 2; nb++)
                    mma_tf32(c[mb][nb][0], c[mb][nb][1], c[mb][nb][2], c[mb][nb][3],
                             a0, a1, a2, a3, wf[kb][nb][0], wf[kb][nb][1]);
            }
        }

        // epilogue: relu + dot(h); C row map: c0/c1 -> gid, c2/c3 -> gid+8
        float lg[4];
        #pragma unroll
        for (int mb = 0; mb < 2; mb++) {
            float a = 0.f, bqq = 0.f;
            #pragma unroll
            for (int nb = 0; nb < 2; nb++) {
                a   = fmaf(fmaxf(c[mb][nb][0], 0.f), hh0[nb], a);
                a   = fmaf(fmaxf(c[mb][nb][1], 0.f), hh1[nb], a);
                bqq = fmaf(fmaxf(c[mb][nb][2], 0.f), hh0[nb], bqq);
                bqq = fmaf(fmaxf(c[mb][nb][3], 0.f), hh1[nb], bqq);
            }
            lg[2*mb]   = a;
            lg[2*mb+1] = bqq;
        }
        #pragma unroll
        for (int s = 0; s < 4; s++) {
            lg[s] += __shfl_xor_sync(0xffffffffu, lg[s], 1);
            lg[s] += __shfl_xor_sync(0xffffffffu, lg[s], 2);
        }
        // all 4 logits replicated across the quad; each lane exps all 4 and
        // FMAs straight into its own acc (rows match its prod regs).
        #pragma unroll
        for (int s = 0; s < 4; s++) {
            float E = (p0 + gid + 8*s < NPAIR) ? __expf(lg[s]) : 0.f;
            lsum += E;
            ull ppE;
            asm("mov.b64 %0, {%1, %1};" : "=l"(ppE) : "f"(E));
            #pragma unroll
            for (int kb = 0; kb < 4; kb++)
                asm("fma.rn.f32x2 %0, %1, %2, %0;"
                    : "+l"(acc[kb]) : "l"(ppE), "l"(prod[kb][s]));
        }
    }

    // ---- reduce pooled partials over gid (lane = 4*gid + tig) ----
    #pragma unroll
    for (int kb = 0; kb < 4; kb++) {
        float lo, hi;
        asm("mov.b64 {%0, %1}, %2;" : "=f"(lo), "=f"(hi) : "l"(acc[kb]));
        #pragma unroll
        for (int o = 4; o < 32; o <<= 1) {
            lo += __shfl_xor_sync(0xffffffffu, lo, o);
            hi += __shfl_xor_sync(0xffffffffu, hi, o);
        }
        if (gid == 0) {
            int d2 = kb*4 + tig;
            poolw[wid][2*d2]   = lo;
            poolw[wid][2*d2+1] = hi;
        }
    }

    // ---- block reduce lsum (4x-replicated) ----
    #pragma unroll
    for (int o = 16; o > 0; o >>= 1) lsum += __shfl_xor_sync(0xffffffffu, lsum, o);
    if (lane == 0) red[wid] = lsum;
    __syncthreads();
    if (tid == 0) {
        float s = 0.f;
        #pragma unroll
        for (int w = 0; w < NW; w++) s += red[w];
        g_sum[bid] = s;
    }
    if (tid < DD) {
        float s = 0.f;
        #pragma unroll
        for (int w = 0; w < NW; w++) s += poolw[w][tid];
        g_pool[bid][tid] = s;
    }

    // ---- last-CTA-done finisher (threadFenceReduction pattern) ----
    __syncthreads();                   // half's g_pool/g_sum stores issued
    if (tid == 0) {
        __threadfence();               // make them visible device-wide
        int old = atomicAdd(&g_cnt[e], 1);
        sFinish = (old == 1);
    }
    __syncthreads();
    if (sFinish) {
        if (tid < DD) {
            __threadfence();           // acquire side before reading peer data
            float stot = g_sum[2*e] + g_sum[2*e + 1];   // = 4 * sum(E)
            float inv  = 4.0f / stot;
            poolv[tid] = (g_pool[2*e][tid] + g_pool[2*e + 1][tid]) * inv;
        }
        __syncthreads();
        if (tid < 16) {
            float z = cb1[tid];
            #pragma unroll
            for (int d = 0; d < DD; d++) z = fmaf(poolv[d], cW1[d*16 + tid], z);
            o1s[tid] = fmaxf(z, 0.f);
        }
        __syncthreads();
        if (tid < 8) {
            float z = cb2[tid];
            #pragma unroll
            for (int c2 = 0; c2 < 16; c2++) z = fmaf(o1s[c2], cW2m[c2*8 + tid], z);
            o2s[tid] = fmaxf(z, 0.f);
        }
        __syncthreads();
        if (tid == 0) {
            float z = cbf[0];
            #pragma unroll
            for (int c2 = 0; c2 < 8; c2++) z = fmaf(o2s[c2], cWf[c2], z);
            out[e] = 1.f / (1.f + __expf(-z));
            g_cnt[e] = 0;              // restore zero-init invariant for next launch
        }
    }
}

extern "C" void kernel_launch(void* const* d_in, const int* in_sizes, int n_in,
                              void* d_out, int out_size) {
    const int*   x   = (const int*)  d_in[0];
    const float* Emb = (const float*)d_in[1];
    const float* Wg  = (const float*)d_in[2];
    float* out = (float*)d_out;

    cudaMemcpyToSymbolAsync(cb,   d_in[3],  AA*sizeof(float),    0, cudaMemcpyDeviceToDevice);
    cudaMemcpyToSymbolAsync(ch,   d_in[4],  AA*sizeof(float),    0, cudaMemcpyDeviceToDevice);
    cudaMemcpyToSymbolAsync(cW1,  d_in[5],  DD*16*sizeof(float), 0, cudaMemcpyDeviceToDevice);
    cudaMemcpyToSymbolAsync(cb1,  d_in[6],  16*sizeof(float),    0, cudaMemcpyDeviceToDevice);
    cudaMemcpyToSymbolAsync(cW2m, d_in[7],  16*8*sizeof(float),  0, cudaMemcpyDeviceToDevice);
    cudaMemcpyToSymbolAsync(cb2,  d_in[8],  8*sizeof(float),     0, cudaMemcpyDeviceToDevice);
    cudaMemcpyToSymbolAsync(cWf,  d_in[9],  8*sizeof(float),     0, cudaMemcpyDeviceToDevice);
    cudaMemcpyToSymbolAsync(cbf,  d_in[10], 1*sizeof(float),     0, cudaMemcpyDeviceToDevice);

    setup_pairs_kernel<<<(NPP + 255)/256, 256>>>();
    afm_half_kernel<<<BSZ*2, NTHREADS>>>(x, Emb, Wg, out);
}

// round 16
// speedup vs baseline: 1.1450x; 1.1450x over previous
#include <cuda_runtime.h>
#include <cstdint>

#define TT 100
#define DD 32
#define AA 16
#define NPAIR 4950
#define NTASK 156
#define HTASK 78            // chunks per half-element
#define NPP (NTASK*32)      // 4992, padded pair space
#define TTP 100
#define NTHREADS 128
#define NW (NTHREADS/32)
#define BSZ 1024

typedef unsigned long long ull;

// ---- compile-time pair table: (i<<8)|j in itertools.combinations order ----
struct PairTab { int v[NPP]; };
static constexpr PairTab make_tab() {
    PairTab t{};
    int p = 0;
    for (int i = 0; i < TT - 1; i++)
        for (int j = i + 1; j < TT; j++)
            t.v[p++] = (i << 8) | j;
    for (; p < NPP; p++) t.v[p] = 1;   // dummy pair (0,1)
    return t;
}
__device__ const PairTab g_tab = make_tab();   // static init in cubin, no setup kernel

// cross-CTA scratch: every slot rewritten each launch (deterministic)
__device__ float g_pool[BSZ*2][DD];   // unnormalized pooled halves
__device__ float g_sum[BSZ*2];        // 4x-replicated exp-sums

// small weights in constant memory
__constant__ __align__(16) float cb[AA];
__constant__ __align__(16) float ch[AA];
__constant__ float cW1[DD*16];
__constant__ float cb1[16];
__constant__ float cW2m[16*8];
__constant__ float cb2[8];
__constant__ float cWf[8];
__constant__ float cbf[1];

__device__ __forceinline__ void mma_tf32(
    float& c0, float& c1, float& c2, float& c3,
    unsigned a0, unsigned a1, unsigned a2, unsigned a3,
    unsigned b0, unsigned b1)
{
    asm volatile(
        "mma.sync.aligned.m16n8k8.row.col.f32.tf32.tf32.f32 "
        "{%0,%1,%2,%3}, {%4,%5,%6,%7}, {%8,%9}, {%0,%1,%2,%3};"
        : "+f"(c0), "+f"(c1), "+f"(c2), "+f"(c3)
        : "r"(a0), "r"(a1), "r"(a2), "r"(a3), "r"(b0), "r"(b1));
}

// ===================== kernel 1: half-element MMA+pool =====================
__global__ __launch_bounds__(NTHREADS, 5) void afm_half_kernel(
    const int*   __restrict__ x,
    const float* __restrict__ Emb,
    const float* __restrict__ Wg)     // [32][16] row-major
{
    __shared__ __align__(16) float2 esT2[AA][TTP];  // [k2][t]: phys dims (2k2, 2k2+1)
    __shared__ int   xs[TT];
    __shared__ float red[NW];
    __shared__ float poolw[NW][DD];   // per-warp pooled partials

    const int tid  = threadIdx.x;
    const int bid  = blockIdx.x;
    const int e    = bid >> 1;        // batch element
    const int hlf  = bid & 1;         // which half of the pair space
    const int lane = tid & 31;
    const int wid  = tid >> 5;
    const int tig  = lane & 3;
    const int gid  = lane >> 2;

    // ---- stage x indices, gather embeddings transposed: esT2[d2][t] ----
    if (tid < TT) xs[tid] = x[e*TT + tid];
    __syncthreads();
    for (int idx = tid; idx < TT*AA; idx += NTHREADS) {
        int t = idx >> 4, d2 = idx & 15;
        float2 v = ((const float2*)Emb)[(size_t)xs[t] * AA + d2];
        esT2[d2][t] = v;
    }

    // ---- per-lane W fragments. K-permutation: fragment col c in {tig, tig+4}
    // of k-block kb maps to PHYSICAL k = kb*8 + 2*tig + (c>=4).
    unsigned wf[4][2][2];
    #pragma unroll
    for (int kb = 0; kb < 4; kb++)
        #pragma unroll
        for (int nb = 0; nb < 2; nb++) {
            wf[kb][nb][0] = __float_as_uint(Wg[(kb*8 + 2*tig    )*16 + nb*8 + gid]);
            wf[kb][nb][1] = __float_as_uint(Wg[(kb*8 + 2*tig + 1)*16 + nb*8 + gid]);
        }
    float bb0[2], bb1[2], hh0[2], hh1[2];
    #pragma unroll
    for (int nb = 0; nb < 2; nb++) {
        bb0[nb] = cb[nb*8 + 2*tig];
        bb1[nb] = cb[nb*8 + 2*tig + 1];
        hh0[nb] = ch[nb*8 + 2*tig];
        hh1[nb] = ch[nb*8 + 2*tig + 1];
    }
    __syncthreads();

    // ============ FUSED: MMA logits -> E -> pooled, over this half ============
    float lsum = 0.f;                 // counts each E 4x (quad-replicated)
    ull acc[4];
    #pragma unroll
    for (int kb = 0; kb < 4; kb++) acc[kb] = 0ull;

    for (int t0 = wid; t0 < HTASK; t0 += NW) {
        const int p0 = (hlf*HTASK + t0)*32;
        int i_[4], j_[4];
        #pragma unroll
        for (int s = 0; s < 4; s++) {
            int v = g_tab.v[p0 + gid + 8*s];
            i_[s] = v >> 8; j_[s] = v & 255;
        }
        float c[2][2][4];
        #pragma unroll
        for (int mb = 0; mb < 2; mb++)
            #pragma unroll
            for (int nb = 0; nb < 2; nb++) {
                c[mb][nb][0] = bb0[nb]; c[mb][nb][1] = bb1[nb];
                c[mb][nb][2] = bb0[nb]; c[mb][nb][3] = bb1[nb];
            }

        ull prod[4][4];   // [kb][s]: product f32x2 for pair row gid+8s, dims k2=kb*4+tig
        #pragma unroll
        for (int kb = 0; kb < 4; kb++) {
            const int k2 = kb*4 + tig;
            #pragma unroll
            for (int mb = 0; mb < 2; mb++) {
                ull eiA = *(const ull*)&esT2[k2][ i_[2*mb]   ];
                ull ejA = *(const ull*)&esT2[k2][ j_[2*mb]   ];
                ull eiB = *(const ull*)&esT2[k2][ i_[2*mb+1] ];
                ull ejB = *(const ull*)&esT2[k2][ j_[2*mb+1] ];
                ull prodA, prodB;
                asm("mul.rn.f32x2 %0, %1, %2;" : "=l"(prodA) : "l"(eiA), "l"(ejA));
                asm("mul.rn.f32x2 %0, %1, %2;" : "=l"(prodB) : "l"(eiB), "l"(ejB));
                prod[kb][2*mb]   = prodA;
                prod[kb][2*mb+1] = prodB;
                unsigned a0, a1, a2, a3;
                asm("mov.b64 {%0,%1}, %2;" : "=r"(a0), "=r"(a2) : "l"(prodA));
                asm("mov.b64 {%0,%1}, %2;" : "=r"(a1), "=r"(a3) : "l"(prodB));
                #pragma unroll
                for (int nb = 0; nb < 2; nb++)
                    mma_tf32(c[mb][nb][0], c[mb][nb][1], c[mb][nb][2], c[mb][nb][3],
                             a0, a1, a2, a3, wf[kb][nb][0], wf[kb][nb][1]);
            }
        }

        // epilogue: relu + dot(h); C row map: c0/c1 -> gid, c2/c3 -> gid+8
        float lg[4];
        #pragma unroll
        for (int mb = 0; mb < 2; mb++) {
            float a = 0.f, bqq = 0.f;
            #pragma unroll
            for (int nb = 0; nb < 2; nb++) {
                a   = fmaf(fmaxf(c[mb][nb][0], 0.f), hh0[nb], a);
                a   = fmaf(fmaxf(c[mb][nb][1], 0.f), hh1[nb], a);
                bqq = fmaf(fmaxf(c[mb][nb][2], 0.f), hh0[nb], bqq);
                bqq = fmaf(fmaxf(c[mb][nb][3], 0.f), hh1[nb], bqq);
            }
            lg[2*mb]   = a;
            lg[2*mb+1] = bqq;
        }
        #pragma unroll
        for (int s = 0; s < 4; s++) {
            lg[s] += __shfl_xor_sync(0xffffffffu, lg[s], 1);
            lg[s] += __shfl_xor_sync(0xffffffffu, lg[s], 2);
        }
        // all 4 logits replicated across the quad; each lane exps all 4 and
        // FMAs straight into its own acc (rows match its prod regs).
        #pragma unroll
        for (int s = 0; s < 4; s++) {
            float E = (p0 + gid + 8*s < NPAIR) ? __expf(lg[s]) : 0.f;
            lsum += E;
            ull ppE;
            asm("mov.b64 %0, {%1, %1};" : "=l"(ppE) : "f"(E));
            #pragma unroll
            for (int kb = 0; kb < 4; kb++)
                asm("fma.rn.f32x2 %0, %1, %2, %0;"
                    : "+l"(acc[kb]) : "l"(ppE), "l"(prod[kb][s]));
        }
    }

    // ---- reduce pooled partials over gid (lane = 4*gid + tig) ----
    #pragma unroll
    for (int kb = 0; kb < 4; kb++) {
        float lo, hi;
        asm("mov.b64 {%0, %1}, %2;" : "=f"(lo), "=f"(hi) : "l"(acc[kb]));
        #pragma unroll
        for (int o = 4; o < 32; o <<= 1) {
            lo += __shfl_xor_sync(0xffffffffu, lo, o);
            hi += __shfl_xor_sync(0xffffffffu, hi, o);
        }
        if (gid == 0) {
            int d2 = kb*4 + tig;
            poolw[wid][2*d2]   = lo;
            poolw[wid][2*d2+1] = hi;
        }
    }

    // ---- block reduce lsum (4x-replicated) ----
    #pragma unroll
    for (int o = 16; o > 0; o >>= 1) lsum += __shfl_xor_sync(0xffffffffu, lsum, o);
    if (lane == 0) red[wid] = lsum;
    __syncthreads();
    if (tid == 0) {
        float s = 0.f;
        #pragma unroll
        for (int w = 0; w < NW; w++) s += red[w];
        g_sum[bid] = s;
    }
    if (tid < DD) {
        float s = 0.f;
        #pragma unroll
        for (int w = 0; w < NW; w++) s += poolw[w][tid];
        g_pool[bid][tid] = s;
    }
}

// ============ kernel 2: combine halves + MLP (one element per thread) ============
__global__ __launch_bounds__(128) void afm_finish_kernel(float* __restrict__ out)
{
    const int e = blockIdx.x * 128 + threadIdx.x;
    if (e >= BSZ) return;

    float stot = g_sum[2*e] + g_sum[2*e + 1];     // = 4 * sum(E)
    float inv  = 4.0f / stot;

    // load both halves as float4 (16 LDG.128), combine + normalize
    float pool[DD];
    const float4* h0 = (const float4*)g_pool[2*e];
    const float4* h1 = (const float4*)g_pool[2*e + 1];
    #pragma unroll
    for (int q = 0; q < DD/4; q++) {
        float4 a = h0[q], b = h1[q];
        pool[4*q+0] = (a.x + b.x) * inv;
        pool[4*q+1] = (a.y + b.y) * inv;
        pool[4*q+2] = (a.z + b.z) * inv;
        pool[4*q+3] = (a.w + b.w) * inv;
    }

    // layer 1: 16 independent accumulators, weights via uniform LDC
    float o1[16];
    #pragma unroll
    for (int c = 0; c < 16; c++) o1[c] = cb1[c];
    #pragma unroll
    for (int d = 0; d < DD; d++)
        #pragma unroll
        for (int c = 0; c < 16; c++)
            o1[c] = fmaf(pool[d], cW1[d*16 + c], o1[c]);

    float o2[8];
    #pragma unroll
    for (int c = 0; c < 8; c++) o2[c] = cb2[c];
    #pragma unroll
    for (int d = 0; d < 16; d++) {
        float v = fmaxf(o1[d], 0.f);
        #pragma unroll
        for (int c = 0; c < 8; c++)
            o2[c] = fmaf(v, cW2m[d*8 + c], o2[c]);
    }

    float z = cbf[0];
    #pragma unroll
    for (int c = 0; c < 8; c++) z = fmaf(fmaxf(o2[c], 0.f), cWf[c], z);
    out[e] = 1.f / (1.f + __expf(-z));
}

extern "C" void kernel_launch(void* const* d_in, const int* in_sizes, int n_in,
                              void* d_out, int out_size) {
    const int*   x   = (const int*)  d_in[0];
    const float* Emb = (const float*)d_in[1];
    const float* Wg  = (const float*)d_in[2];
    float* out = (float*)d_out;

    cudaMemcpyToSymbolAsync(cb,   d_in[3],  AA*sizeof(float),    0, cudaMemcpyDeviceToDevice);
    cudaMemcpyToSymbolAsync(ch,   d_in[4],  AA*sizeof(float),    0, cudaMemcpyDeviceToDevice);
    cudaMemcpyToSymbolAsync(cW1,  d_in[5],  DD*16*sizeof(float), 0, cudaMemcpyDeviceToDevice);
    cudaMemcpyToSymbolAsync(cb1,  d_in[6],  16*sizeof(float),    0, cudaMemcpyDeviceToDevice);
    cudaMemcpyToSymbolAsync(cW2m, d_in[7],  16*8*sizeof(float),  0, cudaMemcpyDeviceToDevice);
    cudaMemcpyToSymbolAsync(cb2,  d_in[8],  8*sizeof(float),     0, cudaMemcpyDeviceToDevice);
    cudaMemcpyToSymbolAsync(cWf,  d_in[9],  8*sizeof(float),     0, cudaMemcpyDeviceToDevice);
    cudaMemcpyToSymbolAsync(cbf,  d_in[10], 1*sizeof(float),     0, cudaMemcpyDeviceToDevice);

    afm_half_kernel<<<BSZ*2, NTHREADS>>>(x, Emb, Wg);
    afm_finish_kernel<<<(BSZ + 127)/128, 128>>>(out);
}